// round 4
// baseline (speedup 1.0000x reference)
#include <cuda_runtime.h>
#include <cuda_bf16.h>
#include <cstdint>

// Problem constants
#define TT      10
#define DD      64
#define HH      4
#define DH      16
#define LL      3
#define FF      256
#define NSEQ    8
#define MM      (NSEQ*TT)   // 80 rows per CTA
#define NTHREADS 256

// Shared memory layout (floats)
#define B_STR   260
#define W_STR   68          // 68 mod 32 = 4 -> conflict-free LDS.128 / STS.128
#define B_ELEMS (MM*B_STR)          // 20800
#define W_ELEMS (64*W_STR)          // 4352
#define SMEM_FLOATS (B_ELEMS + W_ELEMS)
#define SMEM_BYTES  (SMEM_FLOATS*4) // 100608 -> 2 CTAs/SM

// ---------------- packed f32x2 helpers ----------------
__device__ __forceinline__ void fma2(unsigned long long &d,
                                     unsigned long long a,
                                     unsigned long long b) {
    asm("fma.rn.f32x2 %0, %1, %2, %0;" : "+l"(d) : "l"(a), "l"(b));
}
__device__ __forceinline__ float2 unpack2(unsigned long long v) {
    float2 f;
    asm("mov.b64 {%0, %1}, %2;" : "=f"(f.x), "=f"(f.y) : "l"(v));
    return f;
}

// Fast exact-GELU: Abramowitz-Stegun 7.1.26 erf (|abs err| <= 1.5e-7)
__device__ __forceinline__ float gelu_fast(float v) {
    float t = fabsf(v) * 0.70710678118654752f;
    float u = __fdividef(1.0f, fmaf(0.3275911f, t, 1.0f));
    float p = fmaf(1.061405429f, u, -1.453152027f);
    p = fmaf(p, u, 1.421413741f);
    p = fmaf(p, u, -0.284496736f);
    p = fmaf(p, u, 0.254829592f);
    p *= u;
    float e = __expf(-t * t);
    float erf_abs = fmaf(-p, e, 1.0f);
    float sgn = copysignf(erf_abs, v);
    return 0.5f * v * (1.0f + sgn);
}

// 16-lane (half-warp) sum: the 16 lanes differing in bits 0..3 own one row
__device__ __forceinline__ float hsum16(float v) {
    v += __shfl_xor_sync(0xffffffffu, v, 1);
    v += __shfl_xor_sync(0xffffffffu, v, 2);
    v += __shfl_xor_sync(0xffffffffu, v, 4);
    v += __shfl_xor_sync(0xffffffffu, v, 8);
    return v;
}

// ---------------- weight tile staging (64x64), transposed to Wt[j][k] --------
// Each thread owns column j = tid&63, k-groups k4 = (tid>>6)+4i. Global loads
// are coalesced (consecutive j per lane); commit is one STS.128 per group,
// bank-conflict-free with W_STR=68.
struct WFrag { float4 v[4]; };

__device__ __forceinline__ WFrag fetch_w64(const float* __restrict__ g, int gStride) {
    WFrag f;
    const int j  = threadIdx.x & 63;
    const int kb = threadIdx.x >> 6;   // 0..3
#pragma unroll
    for (int i = 0; i < 4; i++) {
        int k4 = kb + 4 * i;           // 0..15
        const float* gp = g + (k4 * 4) * gStride + j;
        float4 v;
        v.x = gp[0];
        v.y = gp[gStride];
        v.z = gp[2 * gStride];
        v.w = gp[3 * gStride];
        f.v[i] = v;
    }
    return f;
}

__device__ __forceinline__ void commit_wt(const WFrag& f, float* __restrict__ wt) {
    const int j  = threadIdx.x & 63;
    const int kb = threadIdx.x >> 6;
#pragma unroll
    for (int i = 0; i < 4; i++) {
        int k4 = kb + 4 * i;
        *reinterpret_cast<float4*>(wt + j * W_STR + k4 * 4) = f.v[i];
    }
}

// ---------------- GEMM tile: [80 x 64] = A[80 x 64] * W[64 x 64] --------------
// tr = tid>>4 (0..15) -> rows tr*5..tr*5+4 ; tc = tid&15 -> cols {tc,tc+16,tc+32,tc+48}
// Residual h lives in registers (hreg[5][4]) with the SAME mapping.
template<bool GELU, bool ACCH, bool STORE, bool LN>
__device__ __forceinline__ void gemm_tile(
    const float* __restrict__ Asm,      // stride B_STR
    const float* __restrict__ wt,
    float (&hreg)[5][4],
    float* __restrict__ Osm,            // stride B_STR (if STORE)
    const float* __restrict__ bias,     // nullptr if none
    float* __restrict__ lnDst,          // stride B_STR (if LN)
    const float* __restrict__ lnG, const float* __restrict__ lnB)
{
    const int tr = threadIdx.x >> 4;
    const int tc = threadIdx.x & 15;
    const float* A0 = Asm + (tr * 5) * B_STR;

    unsigned long long acc[5][4];
#pragma unroll
    for (int u = 0; u < 5; u++)
#pragma unroll
        for (int c = 0; c < 4; c++) acc[u][c] = 0ULL;

#pragma unroll 4
    for (int k4 = 0; k4 < 16; k4++) {
        unsigned long long a0[5], a1[5];
#pragma unroll
        for (int u = 0; u < 5; u++) {
            ulonglong2 av = *reinterpret_cast<const ulonglong2*>(A0 + u * B_STR + k4 * 4);
            a0[u] = av.x;
            a1[u] = av.y;
        }
#pragma unroll
        for (int c = 0; c < 4; c++) {
            ulonglong2 w = *reinterpret_cast<const ulonglong2*>(
                wt + (tc + 16 * c) * W_STR + k4 * 4);
#pragma unroll
            for (int u = 0; u < 5; u++) {
                fma2(acc[u][c], a0[u], w.x);
                fma2(acc[u][c], a1[u], w.y);
            }
        }
    }

    float bv[4], gv[4], bbv[4];
#pragma unroll
    for (int c = 0; c < 4; c++) {
        int j = tc + 16 * c;
        bv[c] = bias ? bias[j] : 0.f;
        if (LN) { gv[c] = lnG[j]; bbv[c] = lnB[j]; }
    }

#pragma unroll
    for (int u = 0; u < 5; u++) {
        float hv[4];
#pragma unroll
        for (int c = 0; c < 4; c++) {
            float2 v = unpack2(acc[u][c]);
            float x = v.x + v.y + bv[c];
            if (GELU) x = gelu_fast(x);
            if (ACCH) { x += hreg[u][c]; hreg[u][c] = x; }
            hv[c] = x;
        }
        if (STORE) {
            float* orow = Osm + (tr * 5 + u) * B_STR;
#pragma unroll
            for (int c = 0; c < 4; c++) orow[tc + 16 * c] = hv[c];
        }
        if (LN) {
            float s  = hv[0] + hv[1] + hv[2] + hv[3];
            float s2 = hv[0]*hv[0] + hv[1]*hv[1] + hv[2]*hv[2] + hv[3]*hv[3];
            s  = hsum16(s);
            s2 = hsum16(s2);
            float m   = s * (1.f / DD);
            float inv = rsqrtf(s2 * (1.f / DD) - m * m + 1e-5f);
            float* lrow = lnDst + (tr * 5 + u) * B_STR;
#pragma unroll
            for (int c = 0; c < 4; c++)
                lrow[tc + 16 * c] = (hv[c] - m) * inv * gv[c] + bbv[c];
        }
    }
}

__global__ __launch_bounds__(NTHREADS, 2)
void waypoint_kernel(
    const float* __restrict__ x,
    const float* __restrict__ embed_w, const float* __restrict__ embed_b,
    const float* __restrict__ ln1_g,   const float* __restrict__ ln1_b,
    const float* __restrict__ qkv_w,   const float* __restrict__ proj_w,
    const float* __restrict__ ln2_g,   const float* __restrict__ ln2_b,
    const float* __restrict__ ffn_w1,  const float* __restrict__ ffn_b1,
    const float* __restrict__ ffn_w2,  const float* __restrict__ ffn_b2,
    const float* __restrict__ lnf_g,   const float* __restrict__ lnf_b,
    const float* __restrict__ head_w,  const float* __restrict__ head_b,
    float* __restrict__ out)
{
    extern __shared__ float smx[];
    float* buf = smx;                // [80][260]
    float* wt  = smx + B_ELEMS;      // [64][68] transposed weight tile

    const int tid = threadIdx.x;
    const int tr  = tid >> 4;
    const int tc  = tid & 15;
    const int rowBase = blockIdx.x * MM;

    float hreg[5][4];                // residual stream, register-resident

    // Prefetch layer-0 qkv tile 0 early (overlaps embed compute)
    WFrag wf = fetch_w64(qkv_w, 3 * DD);

    // -------- embed into hreg (+ fused ln1 of layer 0 -> buf[:,192:256]) -----
    {
        float wcol[4][4], bcol[4], gcol[4], lbcol[4];
#pragma unroll
        for (int c = 0; c < 4; c++) {
            int j = tc + 16 * c;
            wcol[c][0] = embed_w[j];
            wcol[c][1] = embed_w[64 + j];
            wcol[c][2] = embed_w[128 + j];
            wcol[c][3] = embed_w[192 + j];
            bcol[c]  = embed_b[j];
            gcol[c]  = ln1_g[j];
            lbcol[c] = ln1_b[j];
        }
#pragma unroll
        for (int u = 0; u < 5; u++) {
            int r = tr * 5 + u;
            float4 xv = reinterpret_cast<const float4*>(x)[rowBase + r];
            float hv[4];
#pragma unroll
            for (int c = 0; c < 4; c++) {
                float v = bcol[c];
                v = fmaf(xv.x, wcol[c][0], v);
                v = fmaf(xv.y, wcol[c][1], v);
                v = fmaf(xv.z, wcol[c][2], v);
                v = fmaf(xv.w, wcol[c][3], v);
                hreg[u][c] = v;
                hv[c] = v;
            }
            float s  = hv[0] + hv[1] + hv[2] + hv[3];
            float s2 = hv[0]*hv[0] + hv[1]*hv[1] + hv[2]*hv[2] + hv[3]*hv[3];
            s  = hsum16(s);
            s2 = hsum16(s2);
            float m   = s * (1.f / DD);
            float inv = rsqrtf(s2 * (1.f / DD) - m * m + 1e-5f);
            float* lrow = buf + 192 + r * B_STR;
#pragma unroll
            for (int c = 0; c < 4; c++)
                lrow[tc + 16 * c] = (hv[c] - m) * inv * gcol[c] + lbcol[c];
        }
    }

    for (int i = 0; i < LL; i++) {
        const float* l_qkv = qkv_w  + i * DD * 3 * DD;
        const float* l_prj = proj_w + i * DD * DD;
        const float* l_w1  = ffn_w1 + i * DD * FF;
        const float* l_w2  = ffn_w2 + i * FF * DD;

        // -------- qkv: buf[:,0:192] = ln1 @ qkv_w --------
        for (int nt = 0; nt < 3; nt++) {
            __syncthreads();          // prior buf writes + wt free
            commit_wt(wf, wt);
            if (nt < 2)  wf = fetch_w64(l_qkv + (nt + 1) * 64, 3 * DD);
            else         wf = fetch_w64(l_prj, DD);
            __syncthreads();
            gemm_tile<false,false,true,false>(buf + 192, wt, hreg, buf + nt * 64,
                                              nullptr, nullptr, nullptr, nullptr);
        }
        __syncthreads();

        // -------- attention (causal, T=10, dh=16), float4 --------
        {
            int pair = tid >> 3;       // 0..31 : (seq, head)
            int sub  = tid & 7;
            int s  = pair >> 2;        // 0..7
            int hd = pair & 3;         // 0..3
            const float4* qb = reinterpret_cast<const float4*>(buf + hd * DH);
            const float4* kb = reinterpret_cast<const float4*>(buf + 64  + hd * DH);
            const float4* vb = reinterpret_cast<const float4*>(buf + 128 + hd * DH);
            float4* yb = reinterpret_cast<float4*>(buf + 192 + hd * DH);
            const int RS = B_STR / 4;  // 65

            for (int q = sub; q < TT; q += 8) {
                int rq = s * TT + q;
                float4 qv[4];
#pragma unroll
                for (int d = 0; d < 4; d++) qv[d] = qb[rq * RS + d];

                float sc[TT];
                float mx = -1e30f;
                for (int kk = 0; kk <= q; kk++) {
                    const float4* kr = kb + (s * TT + kk) * RS;
                    float a = 0.f;
#pragma unroll
                    for (int d = 0; d < 4; d++) {
                        float4 kv = kr[d];
                        a = fmaf(qv[d].x, kv.x, a);
                        a = fmaf(qv[d].y, kv.y, a);
                        a = fmaf(qv[d].z, kv.z, a);
                        a = fmaf(qv[d].w, kv.w, a);
                    }
                    a *= 0.25f;
                    sc[kk] = a;
                    mx = fmaxf(mx, a);
                }
                float ssum = 0.f;
                for (int kk = 0; kk <= q; kk++) {
                    sc[kk] = __expf(sc[kk] - mx);
                    ssum += sc[kk];
                }
                float inv = __fdividef(1.f, ssum);
                float4 y[4];
#pragma unroll
                for (int d = 0; d < 4; d++) y[d] = make_float4(0.f, 0.f, 0.f, 0.f);
                for (int kk = 0; kk <= q; kk++) {
                    float a = sc[kk] * inv;
                    const float4* vr = vb + (s * TT + kk) * RS;
#pragma unroll
                    for (int d = 0; d < 4; d++) {
                        float4 vv = vr[d];
                        y[d].x = fmaf(a, vv.x, y[d].x);
                        y[d].y = fmaf(a, vv.y, y[d].y);
                        y[d].z = fmaf(a, vv.z, y[d].z);
                        y[d].w = fmaf(a, vv.w, y[d].w);
                    }
                }
#pragma unroll
                for (int d = 0; d < 4; d++) yb[rq * RS + d] = y[d];
            }
        }
        __syncthreads();

        // -------- proj: h += y @ proj_w  (+ fused ln2 -> buf[:,0:64]) --------
        commit_wt(wf, wt);
        wf = fetch_w64(l_w1, FF);
        __syncthreads();
        gemm_tile<false,true,false,true>(buf + 192, wt, hreg, nullptr, nullptr,
                                         buf, ln2_g + i * DD, ln2_b + i * DD);

        // -------- FFN, N tiled 4x64 --------
        for (int ft = 0; ft < 4; ft++) {
            // z = gelu(ln2 @ w1 + b1) -> buf[:,64:128]
            __syncthreads();
            commit_wt(wf, wt);
            wf = fetch_w64(l_w2 + ft * 64 * DD, DD);
            __syncthreads();
            gemm_tile<true,false,true,false>(buf, wt, hreg, buf + 64,
                                             ffn_b1 + i * FF + ft * 64,
                                             nullptr, nullptr, nullptr);
            __syncthreads();

            // h += z @ w2 (+ b2 at ft==0; fused LN at ft==3)
            commit_wt(wf, wt);
            if (ft < 3)      wf = fetch_w64(l_w1 + (ft + 1) * 64, FF);
            else if (i < 2)  wf = fetch_w64(qkv_w + (i + 1) * DD * 3 * DD, 3 * DD);
            else             wf = fetch_w64(qkv_w, 3 * DD);   // harmless tail
            __syncthreads();
            const float* b2 = (ft == 0) ? (ffn_b2 + i * DD) : nullptr;
            if (ft < 3) {
                gemm_tile<false,true,false,false>(buf + 64, wt, hreg, nullptr, b2,
                                                  nullptr, nullptr, nullptr);
            } else if (i < 2) {
                gemm_tile<false,true,false,true>(buf + 64, wt, hreg, nullptr, b2,
                                                 buf + 192,
                                                 ln1_g + (i + 1) * DD, ln1_b + (i + 1) * DD);
            } else {
                gemm_tile<false,true,false,true>(buf + 64, wt, hreg, nullptr, b2,
                                                 buf, lnf_g, lnf_b);
            }
        }
    }
    __syncthreads();

    // -------- head: out[s, j] = lnf[last token] @ head_w + head_b --------
    if (tid < NSEQ * 10) {
        int s = tid / 10;
        int j = tid % 10;
        const float* r = buf + (s * TT + TT - 1) * B_STR;
        float a = head_b[j];
#pragma unroll 16
        for (int d = 0; d < DD; d++) a = fmaf(r[d], head_w[d * 10 + j], a);
        out[(blockIdx.x * NSEQ + s) * 10 + j] = a;
    }
}

extern "C" void kernel_launch(void* const* d_in, const int* in_sizes, int n_in,
                              void* d_out, int out_size)
{
    const float* x       = (const float*)d_in[0];
    const float* embed_w = (const float*)d_in[1];
    const float* embed_b = (const float*)d_in[2];
    const float* ln1_g   = (const float*)d_in[3];
    const float* ln1_b   = (const float*)d_in[4];
    const float* qkv_w   = (const float*)d_in[5];
    const float* proj_w  = (const float*)d_in[6];
    const float* ln2_g   = (const float*)d_in[7];
    const float* ln2_b   = (const float*)d_in[8];
    const float* ffn_w1  = (const float*)d_in[9];
    const float* ffn_b1  = (const float*)d_in[10];
    const float* ffn_w2  = (const float*)d_in[11];
    const float* ffn_b2  = (const float*)d_in[12];
    const float* lnf_g   = (const float*)d_in[13];
    const float* lnf_b   = (const float*)d_in[14];
    const float* head_w  = (const float*)d_in[15];
    const float* head_b  = (const float*)d_in[16];
    float* out = (float*)d_out;

    int nTokens = in_sizes[0] / 4;
    int nB = nTokens / TT;
    int grid = nB / NSEQ;              // 2048

    cudaFuncSetAttribute(waypoint_kernel,
                         cudaFuncAttributeMaxDynamicSharedMemorySize, SMEM_BYTES);

    waypoint_kernel<<<grid, NTHREADS, SMEM_BYTES>>>(
        x, embed_w, embed_b, ln1_g, ln1_b, qkv_w, proj_w,
        ln2_g, ln2_b, ffn_w1, ffn_b1, ffn_w2, ffn_b2,
        lnf_g, lnf_b, head_w, head_b, out);
}